// round 3
// baseline (speedup 1.0000x reference)
#include <cuda_runtime.h>
#include <cuda_bf16.h>

// Problem constants
#define BB 32
#define CC_ 256
#define OO 256
#define HH 56
#define WW 56
#define CHK 4
#define HW (HH*WW)

// Conv tiling constants
#define TOC 32      // output channels per block
#define CCH 16      // input channels per smem chunk
#define NOCB (OO/TOC)       // 8 oc blocks
#define NCCH (CC_/CCH)      // 16 channel chunks

// ---------------- scratch (device globals: allocation-free) ----------------
__device__ float g_pooled[BB*CC_];
__device__ float g_h[BB*CC_];
__device__ float g_kern[BB*CC_*CHK];
// dyn_w stored in the conv kernel's tiled layout:
// [b][ocb(8)][cchunk(16)][c_local(16)][k(9)][oc_local(32)]
__device__ float g_dynw[(size_t)BB*OO*CC_*9];

// ---------------- kernel 1: global average pool ----------------
__global__ __launch_bounds__(128) void pool_kernel(const float* __restrict__ x) {
    int bc = blockIdx.x;                         // 0 .. B*C-1
    const float4* xp = (const float4*)(x + (size_t)bc * HW);
    float s = 0.f;
    for (int i = threadIdx.x; i < HW/4; i += 128) {
        float4 v = xp[i];
        s += (v.x + v.y) + (v.z + v.w);
    }
    // warp reduce
    for (int off = 16; off > 0; off >>= 1)
        s += __shfl_down_sync(0xffffffffu, s, off);
    __shared__ float red[4];
    if ((threadIdx.x & 31) == 0) red[threadIdx.x >> 5] = s;
    __syncthreads();
    if (threadIdx.x == 0) {
        float t = red[0] + red[1] + red[2] + red[3];
        g_pooled[bc] = t * (1.0f / (float)HW);
    }
}

// ---------------- kernel 2: h = relu(pooled @ fc1_w^T) ----------------
__global__ __launch_bounds__(256) void fc1_kernel(const float* __restrict__ fc1_w) {
    int b = blockIdx.x;
    int i = threadIdx.x;                          // output channel
    __shared__ float sp[CC_];
    sp[i] = g_pooled[b*CC_ + i];
    __syncthreads();
    const float* wr = fc1_w + (size_t)i * CC_;
    float s = 0.f;
    #pragma unroll 8
    for (int k = 0; k < CC_; ++k) s = fmaf(sp[k], wr[k], s);
    g_h[b*CC_ + i] = fmaxf(s, 0.f);
}

// ---------------- kernel 3: kern = h @ fc2_w^T + fc2_b ----------------
__global__ __launch_bounds__(1024) void fc2_kernel(const float* __restrict__ fc2_w,
                                                   const float* __restrict__ fc2_b) {
    int b = blockIdx.x;
    int j = threadIdx.x;                          // 0..1023
    __shared__ float sh[CC_];
    if (j < CC_) sh[j] = g_h[b*CC_ + j];
    __syncthreads();
    const float* wr = fc2_w + (size_t)j * CC_;
    float s = fc2_b[j];
    #pragma unroll 8
    for (int k = 0; k < CC_; ++k) s = fmaf(sh[k], wr[k], s);
    g_kern[b*(CC_*CHK) + j] = s;
}

// ---------------- kernel 4: dyn_w = sigmoid(einsum) * weight ----------------
// Writes in the conv's tiled layout. One thread per element (linear in output).
__global__ __launch_bounds__(256) void dynw_kernel(const float* __restrict__ cog,
                                                   const float* __restrict__ weight) {
    int idx = blockIdx.x * 256 + threadIdx.x;     // < B*O*C*9 = 18,874,368
    int ocl = idx & 31;
    int t0  = idx >> 5;
    int k   = t0 % 9;
    int t1  = t0 / 9;
    int cl  = t1 & 15;
    int t2  = t1 >> 4;
    int cch = t2 & 15;
    int t3  = t2 >> 4;
    int ocb = t3 & 7;
    int b   = t3 >> 3;

    int o = ocb*TOC + ocl;
    int c = cch*CCH + cl;

    const float* kp = g_kern + b*(CC_*CHK) + c*CHK;
    float cw = 0.f;
    #pragma unroll
    for (int t = 0; t < CHK; ++t)
        cw = fmaf(kp[t], cog[(o*CHK + t)*9 + k], cw);
    float sg = __fdividef(1.0f, 1.0f + __expf(-cw));
    g_dynw[idx] = sg * weight[((size_t)o*CC_ + c)*9 + k];
}

// ---------------- kernel 5: per-sample 3x3 conv ----------------
// Block: 128 threads. Tile: 32 oc x 8x8 pixels. Thread: 4 oc x 2x2 px.
__global__ __launch_bounds__(128) void conv_kernel(const float* __restrict__ x,
                                                   float* __restrict__ out) {
    const int sp  = blockIdx.x;       // 0..48 spatial tile (7x7)
    const int ocb = blockIdx.y;       // 0..7
    const int b   = blockIdx.z;       // 0..31
    const int ty0 = (sp / 7) * 8;
    const int tx0 = (sp % 7) * 8;

    const int tid    = threadIdx.x;
    const int oc_sub = tid >> 4;      // 0..7
    const int px_sub = tid & 15;
    const int pr2    = (px_sub >> 2) * 2;   // 0,2,4,6
    const int pc2    = (px_sub & 3) * 2;    // 0,2,4,6
    const int oc4    = oc_sub * 4;

    __shared__ float xs[CCH][10][12];            // padded to 12 -> conflict-free
    __shared__ float ws[CCH*9*TOC];              // [c][k][oc], linear

    float acc[4][2][2];
    #pragma unroll
    for (int i = 0; i < 4; ++i)
        #pragma unroll
        for (int dy = 0; dy < 2; ++dy)
            #pragma unroll
            for (int dx = 0; dx < 2; ++dx) acc[i][dy][dx] = 0.f;

    const float* xb = x + (size_t)b * CC_ * HW;
    const float4* wbase = (const float4*)(g_dynw + ((size_t)(b*NOCB + ocb) * NCCH) * (CCH*9*TOC));
    float4* wdst = (float4*)ws;

    for (int cc = 0; cc < NCCH; ++cc) {
        // --- stage x halo: 16 ch x 10 x 10 (zero-padded borders) ---
        for (int i = tid; i < CCH*100; i += 128) {
            int c  = i / 100;
            int r  = i - c*100;
            int yy = r / 10;
            int xx = r - yy*10;
            int gy = ty0 - 1 + yy;
            int gx = tx0 - 1 + xx;
            float v = 0.f;
            if ((unsigned)gy < (unsigned)HH && (unsigned)gx < (unsigned)WW)
                v = xb[(cc*CCH + c)*HW + gy*WW + gx];
            xs[c][yy][xx] = v;
        }
        // --- stage weights: contiguous 4608 floats, float4 copy ---
        const float4* wsrc = wbase + (size_t)cc * (CCH*9*TOC/4);
        #pragma unroll
        for (int i = 0; i < 9; ++i)              // 1152 float4 / 128 threads
            wdst[tid + i*128] = wsrc[tid + i*128];
        __syncthreads();

        #pragma unroll 4
        for (int c = 0; c < CCH; ++c) {
            // 4x4 input patch for this thread's 2x2 outputs
            float xv[4][4];
            #pragma unroll
            for (int y = 0; y < 4; ++y) {
                float2 a  = *(const float2*)&xs[c][pr2 + y][pc2];
                float2 b2 = *(const float2*)&xs[c][pr2 + y][pc2 + 2];
                xv[y][0] = a.x;  xv[y][1] = a.y;
                xv[y][2] = b2.x; xv[y][3] = b2.y;
            }
            #pragma unroll
            for (int ky = 0; ky < 3; ++ky) {
                #pragma unroll
                for (int kx = 0; kx < 3; ++kx) {
                    float4 w = *(const float4*)&ws[(c*9 + ky*3 + kx)*TOC + oc4];
                    #pragma unroll
                    for (int dy = 0; dy < 2; ++dy) {
                        #pragma unroll
                        for (int dx = 0; dx < 2; ++dx) {
                            float xvv = xv[ky + dy][kx + dx];
                            acc[0][dy][dx] = fmaf(w.x, xvv, acc[0][dy][dx]);
                            acc[1][dy][dx] = fmaf(w.y, xvv, acc[1][dy][dx]);
                            acc[2][dy][dx] = fmaf(w.z, xvv, acc[2][dy][dx]);
                            acc[3][dy][dx] = fmaf(w.w, xvv, acc[3][dy][dx]);
                        }
                    }
                }
            }
        }
        __syncthreads();
    }

    // --- epilogue: float2 stores ---
    #pragma unroll
    for (int i = 0; i < 4; ++i) {
        int oc = ocb*TOC + oc4 + i;
        float* op = out + (size_t)(b*OO + oc) * HW;
        #pragma unroll
        for (int dy = 0; dy < 2; ++dy) {
            float2 v = make_float2(acc[i][dy][0], acc[i][dy][1]);
            *(float2*)&op[(ty0 + pr2 + dy)*WW + tx0 + pc2] = v;
        }
    }
}

// ---------------- launcher ----------------
extern "C" void kernel_launch(void* const* d_in, const int* in_sizes, int n_in,
                              void* d_out, int out_size) {
    const float* x     = (const float*)d_in[0];
    const float* fc1_w = (const float*)d_in[1];
    const float* fc2_w = (const float*)d_in[2];
    const float* fc2_b = (const float*)d_in[3];
    const float* cog   = (const float*)d_in[4];
    const float* weight= (const float*)d_in[5];
    float* out = (float*)d_out;

    pool_kernel<<<BB*CC_, 128>>>(x);
    fc1_kernel<<<BB, 256>>>(fc1_w);
    fc2_kernel<<<BB, 1024>>>(fc2_w, fc2_b);
    dynw_kernel<<<(BB*OO*CC_*9)/256, 256>>>(cog, weight);
    dim3 grid(49, NOCB, BB);
    conv_kernel<<<grid, 128>>>(x, out);
}

// round 5
// speedup vs baseline: 1.0009x; 1.0009x over previous
#include <cuda_runtime.h>
#include <cuda_bf16.h>

// Problem constants
#define BB 32
#define CC_ 256
#define OO 256
#define HH 56
#define WW 56
#define CHK 4
#define HW (HH*WW)

// Conv tiling constants
#define TOC 32      // output channels per block
#define CCH 16      // input channels per smem chunk
#define NOCB (OO/TOC)       // 8 oc blocks
#define NCCH (CC_/CCH)      // 16 channel chunks

// ---------------- scratch (device globals: allocation-free) ----------------
__device__ float g_pooled[BB*CC_];
__device__ float g_h[BB*CC_];
__device__ float g_kern[BB*CC_*CHK];
// dyn_w stored in the conv kernel's tiled layout:
// [b][ocb(8)][cchunk(16)][c_local(16)][k(9)][oc_local(32)]
__device__ float g_dynw[(size_t)BB*OO*CC_*9];

// ---------------- kernel 1: global average pool ----------------
__global__ __launch_bounds__(128) void pool_kernel(const float* __restrict__ x) {
    int bc = blockIdx.x;                         // 0 .. B*C-1
    const float4* xp = (const float4*)(x + (size_t)bc * HW);
    float s = 0.f;
    for (int i = threadIdx.x; i < HW/4; i += 128) {
        float4 v = xp[i];
        s += (v.x + v.y) + (v.z + v.w);
    }
    // warp reduce
    for (int off = 16; off > 0; off >>= 1)
        s += __shfl_down_sync(0xffffffffu, s, off);
    __shared__ float red[4];
    if ((threadIdx.x & 31) == 0) red[threadIdx.x >> 5] = s;
    __syncthreads();
    if (threadIdx.x == 0) {
        float t = red[0] + red[1] + red[2] + red[3];
        g_pooled[bc] = t * (1.0f / (float)HW);
    }
}

// ---------------- kernel 2: h = relu(pooled @ fc1_w^T) ----------------
__global__ __launch_bounds__(256) void fc1_kernel(const float* __restrict__ fc1_w) {
    int b = blockIdx.x;
    int i = threadIdx.x;                          // output channel
    __shared__ float sp[CC_];
    sp[i] = g_pooled[b*CC_ + i];
    __syncthreads();
    const float* wr = fc1_w + (size_t)i * CC_;
    float s = 0.f;
    #pragma unroll 8
    for (int k = 0; k < CC_; ++k) s = fmaf(sp[k], wr[k], s);
    g_h[b*CC_ + i] = fmaxf(s, 0.f);
}

// ---------------- kernel 3: kern = h @ fc2_w^T + fc2_b ----------------
__global__ __launch_bounds__(1024) void fc2_kernel(const float* __restrict__ fc2_w,
                                                   const float* __restrict__ fc2_b) {
    int b = blockIdx.x;
    int j = threadIdx.x;                          // 0..1023
    __shared__ float sh[CC_];
    if (j < CC_) sh[j] = g_h[b*CC_ + j];
    __syncthreads();
    const float* wr = fc2_w + (size_t)j * CC_;
    float s = fc2_b[j];
    #pragma unroll 8
    for (int k = 0; k < CC_; ++k) s = fmaf(sh[k], wr[k], s);
    g_kern[b*(CC_*CHK) + j] = s;
}

// ---------------- kernel 4: dyn_w = sigmoid(einsum) * weight ----------------
// Writes in the conv's tiled layout. One thread per element (linear in output).
__global__ __launch_bounds__(256) void dynw_kernel(const float* __restrict__ cog,
                                                   const float* __restrict__ weight) {
    int idx = blockIdx.x * 256 + threadIdx.x;     // < B*O*C*9 = 18,874,368
    int ocl = idx & 31;
    int t0  = idx >> 5;
    int k   = t0 % 9;
    int t1  = t0 / 9;
    int cl  = t1 & 15;
    int t2  = t1 >> 4;
    int cch = t2 & 15;
    int t3  = t2 >> 4;
    int ocb = t3 & 7;
    int b   = t3 >> 3;

    int o = ocb*TOC + ocl;
    int c = cch*CCH + cl;

    const float* kp = g_kern + b*(CC_*CHK) + c*CHK;
    float cw = 0.f;
    #pragma unroll
    for (int t = 0; t < CHK; ++t)
        cw = fmaf(kp[t], cog[(o*CHK + t)*9 + k], cw);
    float sg = __fdividef(1.0f, 1.0f + __expf(-cw));
    g_dynw[idx] = sg * weight[((size_t)o*CC_ + c)*9 + k];
}

// ---------------- kernel 5: per-sample 3x3 conv ----------------
// Block: 128 threads. Tile: 32 oc x 8x8 pixels. Thread: 4 oc x 2x2 px.
__global__ __launch_bounds__(128) void conv_kernel(const float* __restrict__ x,
                                                   float* __restrict__ out) {
    const int sp  = blockIdx.x;       // 0..48 spatial tile (7x7)
    const int ocb = blockIdx.y;       // 0..7
    const int b   = blockIdx.z;       // 0..31
    const int ty0 = (sp / 7) * 8;
    const int tx0 = (sp % 7) * 8;

    const int tid    = threadIdx.x;
    const int oc_sub = tid >> 4;      // 0..7
    const int px_sub = tid & 15;
    const int pr2    = (px_sub >> 2) * 2;   // 0,2,4,6
    const int pc2    = (px_sub & 3) * 2;    // 0,2,4,6
    const int oc4    = oc_sub * 4;

    __shared__ float xs[CCH][10][12];            // padded to 12 -> conflict-free
    __shared__ float ws[CCH*9*TOC];              // [c][k][oc], linear

    float acc[4][2][2];
    #pragma unroll
    for (int i = 0; i < 4; ++i)
        #pragma unroll
        for (int dy = 0; dy < 2; ++dy)
            #pragma unroll
            for (int dx = 0; dx < 2; ++dx) acc[i][dy][dx] = 0.f;

    const float* xb = x + (size_t)b * CC_ * HW;
    const float4* wbase = (const float4*)(g_dynw + ((size_t)(b*NOCB + ocb) * NCCH) * (CCH*9*TOC));
    float4* wdst = (float4*)ws;

    for (int cc = 0; cc < NCCH; ++cc) {
        // --- stage x halo: 16 ch x 10 x 10 (zero-padded borders) ---
        for (int i = tid; i < CCH*100; i += 128) {
            int c  = i / 100;
            int r  = i - c*100;
            int yy = r / 10;
            int xx = r - yy*10;
            int gy = ty0 - 1 + yy;
            int gx = tx0 - 1 + xx;
            float v = 0.f;
            if ((unsigned)gy < (unsigned)HH && (unsigned)gx < (unsigned)WW)
                v = xb[(cc*CCH + c)*HW + gy*WW + gx];
            xs[c][yy][xx] = v;
        }
        // --- stage weights: contiguous 4608 floats, float4 copy ---
        const float4* wsrc = wbase + (size_t)cc * (CCH*9*TOC/4);
        #pragma unroll
        for (int i = 0; i < 9; ++i)              // 1152 float4 / 128 threads
            wdst[tid + i*128] = wsrc[tid + i*128];
        __syncthreads();

        #pragma unroll 4
        for (int c = 0; c < CCH; ++c) {
            // 4x4 input patch for this thread's 2x2 outputs
            float xv[4][4];
            #pragma unroll
            for (int y = 0; y < 4; ++y) {
                float2 a  = *(const float2*)&xs[c][pr2 + y][pc2];
                float2 b2 = *(const float2*)&xs[c][pr2 + y][pc2 + 2];
                xv[y][0] = a.x;  xv[y][1] = a.y;
                xv[y][2] = b2.x; xv[y][3] = b2.y;
            }
            #pragma unroll
            for (int ky = 0; ky < 3; ++ky) {
                #pragma unroll
                for (int kx = 0; kx < 3; ++kx) {
                    float4 w = *(const float4*)&ws[(c*9 + ky*3 + kx)*TOC + oc4];
                    #pragma unroll
                    for (int dy = 0; dy < 2; ++dy) {
                        #pragma unroll
                        for (int dx = 0; dx < 2; ++dx) {
                            float xvv = xv[ky + dy][kx + dx];
                            acc[0][dy][dx] = fmaf(w.x, xvv, acc[0][dy][dx]);
                            acc[1][dy][dx] = fmaf(w.y, xvv, acc[1][dy][dx]);
                            acc[2][dy][dx] = fmaf(w.z, xvv, acc[2][dy][dx]);
                            acc[3][dy][dx] = fmaf(w.w, xvv, acc[3][dy][dx]);
                        }
                    }
                }
            }
        }
        __syncthreads();
    }

    // --- epilogue: float2 stores ---
    #pragma unroll
    for (int i = 0; i < 4; ++i) {
        int oc = ocb*TOC + oc4 + i;
        float* op = out + (size_t)(b*OO + oc) * HW;
        #pragma unroll
        for (int dy = 0; dy < 2; ++dy) {
            float2 v = make_float2(acc[i][dy][0], acc[i][dy][1]);
            *(float2*)&op[(ty0 + pr2 + dy)*WW + tx0 + pc2] = v;
        }
    }
}

// ---------------- launcher ----------------
extern "C" void kernel_launch(void* const* d_in, const int* in_sizes, int n_in,
                              void* d_out, int out_size) {
    const float* x     = (const float*)d_in[0];
    const float* fc1_w = (const float*)d_in[1];
    const float* fc2_w = (const float*)d_in[2];
    const float* fc2_b = (const float*)d_in[3];
    const float* cog   = (const float*)d_in[4];
    const float* weight= (const float*)d_in[5];
    float* out = (float*)d_out;

    pool_kernel<<<BB*CC_, 128>>>(x);
    fc1_kernel<<<BB, 256>>>(fc1_w);
    fc2_kernel<<<BB, 1024>>>(fc2_w, fc2_b);
    dynw_kernel<<<(BB*OO*CC_*9)/256, 256>>>(cog, weight);
    dim3 grid(49, NOCB, BB);
    conv_kernel<<<grid, 128>>>(x, out);
}